// round 10
// baseline (speedup 1.0000x reference)
#include <cuda_runtime.h>
#include <cuda_fp16.h>
#include <math_constants.h>

// Problem constants
#define BB 4
#define NN 2048
#define DD 512
#define HH 8
#define KD 64
#define QSCALE 0.18033688011112042f   // (1/sqrt(64)) * log2(e)

// Scratch (static device globals -- no runtime allocation)
__device__ __half g_Xh[(size_t)BB * NN * DD];
__device__ __half g_Wqh[DD * DD];   // pre-scaled by QSCALE
__device__ __half g_Wkh[DD * DD];
__device__ __half g_Wch[DD * DD];
__device__ __half g_Qh[(size_t)BB * NN * DD];
__device__ __half g_Kh[(size_t)BB * NN * DD];
__device__ __half g_Oh[(size_t)BB * NN * DD];
__device__ unsigned int g_Mbits[(size_t)BB * NN * (NN / 32)];
__device__ int g_mask_is_byte;

// ---------------------------------------------------------------------------
// helpers
// ---------------------------------------------------------------------------
__device__ __forceinline__ unsigned smem_u32(const void* p)
{
    return (unsigned)__cvta_generic_to_shared(p);
}

__device__ __forceinline__ void cp16(unsigned d, const void* s)
{
    asm volatile("cp.async.ca.shared.global [%0], [%1], 16;" :: "r"(d), "l"(s));
}
__device__ __forceinline__ void cp4(unsigned d, const void* s)
{
    asm volatile("cp.async.ca.shared.global [%0], [%1], 4;" :: "r"(d), "l"(s));
}
#define CP_COMMIT() asm volatile("cp.async.commit_group;")
#define CP_WAIT1()  asm volatile("cp.async.wait_group 1;")
#define CP_WAIT0()  asm volatile("cp.async.wait_group 0;")

__device__ __forceinline__ void ldsm_x4(unsigned& r0, unsigned& r1,
                                        unsigned& r2, unsigned& r3, unsigned a)
{
    asm volatile("ldmatrix.sync.aligned.m8n8.x4.shared.b16 {%0,%1,%2,%3}, [%4];"
                 : "=r"(r0), "=r"(r1), "=r"(r2), "=r"(r3) : "r"(a));
}

__device__ __forceinline__ void ldsm_x4t(unsigned& r0, unsigned& r1,
                                         unsigned& r2, unsigned& r3, unsigned a)
{
    asm volatile("ldmatrix.sync.aligned.m8n8.x4.trans.shared.b16 {%0,%1,%2,%3}, [%4];"
                 : "=r"(r0), "=r"(r1), "=r"(r2), "=r"(r3) : "r"(a));
}

__device__ __forceinline__ void mma_h(float* c, const unsigned* a,
                                      unsigned b0, unsigned b1)
{
    asm volatile(
        "mma.sync.aligned.m16n8k16.row.col.f32.f16.f16.f32 "
        "{%0,%1,%2,%3},{%4,%5,%6,%7},{%8,%9},{%0,%1,%2,%3};"
        : "+f"(c[0]), "+f"(c[1]), "+f"(c[2]), "+f"(c[3])
        : "r"(a[0]), "r"(a[1]), "r"(a[2]), "r"(a[3]), "r"(b0), "r"(b1));
}

__device__ __forceinline__ float ex2(float x)
{
    float r;
    asm("ex2.approx.f32 %0, %1;" : "=f"(r) : "f"(x));
    return r;
}

__device__ __forceinline__ unsigned packh2(float a, float b)
{
    __half2 h = __floats2half2_rn(a, b);
    return *(unsigned*)&h;
}

// ---------------------------------------------------------------------------
// Mask dtype detection + bit compression
// ---------------------------------------------------------------------------
__global__ void detect_mask_kind(const unsigned int* __restrict__ m)
{
    __shared__ int s_byte;
    if (threadIdx.x == 0) s_byte = 0;
    __syncthreads();
    int local = 0;
    for (int i = threadIdx.x; i < 16384; i += blockDim.x) {
        unsigned int w = m[i];
        if (w != 0u && w != 1u && w != 0x3F800000u) local = 1;
    }
    if (local) s_byte = 1;
    __syncthreads();
    if (threadIdx.x == 0) g_mask_is_byte = s_byte;
}

__global__ void mask_to_bits(const unsigned char* __restrict__ mask)
{
    int idx = blockIdx.x * 256 + threadIdx.x;
    size_t row = (size_t)(idx >> 6);
    int w = idx & 63;
    unsigned int bits = 0;
    if (g_mask_is_byte) {
        const uint4* p = (const uint4*)(mask + row * NN + w * 32);
        uint4 A = p[0], Bv = p[1];
        unsigned int ws[8] = {A.x, A.y, A.z, A.w, Bv.x, Bv.y, Bv.z, Bv.w};
#pragma unroll
        for (int i = 0; i < 8; i++) {
            unsigned int v = ws[i];
            bits |= ((v >> 0)  & 1u) << (i * 4 + 0);
            bits |= ((v >> 8)  & 1u) << (i * 4 + 1);
            bits |= ((v >> 16) & 1u) << (i * 4 + 2);
            bits |= ((v >> 24) & 1u) << (i * 4 + 3);
        }
    } else {
        const uint4* p = (const uint4*)mask + row * (NN / 4) + w * 8;
#pragma unroll
        for (int i = 0; i < 8; i++) {
            uint4 t = p[i];
            bits |= (unsigned)(t.x != 0u) << (i * 4 + 0);
            bits |= (unsigned)(t.y != 0u) << (i * 4 + 1);
            bits |= (unsigned)(t.z != 0u) << (i * 4 + 2);
            bits |= (unsigned)(t.w != 0u) << (i * 4 + 3);
        }
    }
    g_Mbits[idx] = bits;
}

// ---------------------------------------------------------------------------
// fused fp32 -> fp16 conversion: covers X (4M elems) then Wq/Wk/Wc (256K each)
// ---------------------------------------------------------------------------
#define XELEMS ((size_t)BB * NN * DD)
#define WELEMS ((size_t)DD * DD)

__global__ void conv_all_kernel(const float* __restrict__ X,
                                const float* __restrict__ Wq,
                                const float* __restrict__ Wk,
                                const float* __restrict__ Wc)
{
    size_t i = ((size_t)blockIdx.x * 256 + threadIdx.x) * 8;
    const float* s;
    __half* d;
    float sc = 1.0f;
    if (i < XELEMS) {
        s = X + i;            d = g_Xh + i;
    } else if (i < XELEMS + WELEMS) {
        s = Wq + (i - XELEMS);            d = g_Wqh + (i - XELEMS);  sc = QSCALE;
    } else if (i < XELEMS + 2 * WELEMS) {
        s = Wk + (i - XELEMS - WELEMS);   d = g_Wkh + (i - XELEMS - WELEMS);
    } else {
        s = Wc + (i - XELEMS - 2 * WELEMS); d = g_Wch + (i - XELEMS - 2 * WELEMS);
    }
    float4 f0 = *(const float4*)s;
    float4 f1 = *(const float4*)(s + 4);
    *(uint4*)d = make_uint4(
        packh2(f0.x * sc, f0.y * sc), packh2(f0.z * sc, f0.w * sc),
        packh2(f1.x * sc, f1.y * sc), packh2(f1.z * sc, f1.w * sc));
}

// ---------------------------------------------------------------------------
// fp16 tensor-core GEMM with cp.async double buffering.
// (Round-6 version: 8 warps, 32x64 warp tile -- best measured.)
// ---------------------------------------------------------------------------
#define GP 40
#define GBUF (128 * GP)

__global__ __launch_bounds__(256) void gemm_h_kernel(
    const __half* __restrict__ X,
    const __half* __restrict__ W0, const __half* __restrict__ W1,
    void* __restrict__ C0, void* __restrict__ C1, int out_half)
{
    __shared__ __half Xs[2 * GBUF];
    __shared__ __half Ws[2 * GBUF];

    const __half* __restrict__ W = (blockIdx.z == 0) ? W0 : W1;
    void* __restrict__ C = (blockIdx.z == 0) ? C0 : C1;

    const int bm = blockIdx.x * 128;
    const int bn = blockIdx.y * 128;
    const int tid = threadIdx.x;
    const int w = tid >> 5;
    const int lane = tid & 31;
    const int g = lane >> 2;
    const int c = lane & 3;
    const int wm = w & 3;
    const int wn = w >> 2;

    const unsigned xs0 = smem_u32(Xs);
    const unsigned ws0 = smem_u32(Ws);

    const int sr = tid >> 1;
    const int sg16 = (tid & 1) * 16;

    float acc[16][4];
#pragma unroll
    for (int i = 0; i < 16; i++)
#pragma unroll
        for (int j = 0; j < 4; j++) acc[i][j] = 0.f;

    const __half* xsrc = X + (size_t)(bm + sr) * 512 + sg16;
    const __half* wsrc = W + (size_t)(bn + sr) * 512 + sg16;
    const unsigned xdst = xs0 + (sr * GP + sg16) * 2;
    const unsigned wdst = ws0 + (sr * GP + sg16) * 2;

    cp16(xdst, xsrc);            cp16(xdst + 16, xsrc + 8);
    cp16(wdst, wsrc);            cp16(wdst + 16, wsrc + 8);
    CP_COMMIT();

    const int lrow = lane & 15;
    const int lcol = (lane >> 4) * 8;

    for (int t = 0; t < 16; t++) {
        const int buf = t & 1;
        if (t < 15) {
            int k0 = (t + 1) * 32;
            unsigned off = (buf ^ 1) * GBUF * 2;
            cp16(xdst + off, xsrc + k0);      cp16(xdst + off + 16, xsrc + k0 + 8);
            cp16(wdst + off, wsrc + k0);      cp16(wdst + off + 16, wsrc + k0 + 8);
            CP_COMMIT();
            CP_WAIT1();
        } else {
            CP_WAIT0();
        }
        __syncthreads();

        const unsigned xb = xs0 + buf * GBUF * 2;
        const unsigned wb = ws0 + buf * GBUF * 2;
#pragma unroll
        for (int kk = 0; kk < 2; kk++) {
            unsigned am[2][4];
#pragma unroll
            for (int mi = 0; mi < 2; mi++) {
                unsigned a = xb + ((wm * 32 + mi * 16 + lrow) * GP + kk * 16 + lcol) * 2;
                ldsm_x4(am[mi][0], am[mi][1], am[mi][2], am[mi][3], a);
            }
#pragma unroll
            for (int ng = 0; ng < 4; ng++) {
                unsigned r0, r1, r2, r3;
                unsigned a = wb + ((wn * 64 + ng * 16 + lrow) * GP + kk * 16 + lcol) * 2;
                ldsm_x4(r0, r1, r2, r3, a);
                mma_h(acc[0 * 8 + 2 * ng],     am[0], r0, r2);
                mma_h(acc[0 * 8 + 2 * ng + 1], am[0], r1, r3);
                mma_h(acc[1 * 8 + 2 * ng],     am[1], r0, r2);
                mma_h(acc[1 * 8 + 2 * ng + 1], am[1], r1, r3);
            }
        }
        __syncthreads();
    }

#pragma unroll
    for (int mi = 0; mi < 2; mi++) {
#pragma unroll
        for (int nf = 0; nf < 8; nf++) {
            const float* a = acc[mi * 8 + nf];
            size_t grow = (size_t)(bm + wm * 32 + mi * 16 + g);
            int col = bn + wn * 64 + nf * 8 + 2 * c;
            if (out_half) {
                __half* Ch = (__half*)C;
                *(unsigned*)&Ch[grow * 512 + col]       = packh2(a[0], a[1]);
                *(unsigned*)&Ch[(grow + 8) * 512 + col] = packh2(a[2], a[3]);
            } else {
                float* Cf = (float*)C;
                *(float2*)&Cf[grow * 512 + col]       = make_float2(a[0], a[1]);
                *(float2*)&Cf[(grow + 8) * 512 + col] = make_float2(a[2], a[3]);
            }
        }
    }
}

// ---------------------------------------------------------------------------
// fp16 tensor-core flash attention (V = K), cp.async double buffering.
// Round-6 structure; __launch_bounds__(256, 3) caps regs at ~85 so THREE
// blocks (24 warps) fit per SM instead of two (occupancy 21% -> ~32%).
// ---------------------------------------------------------------------------
#define KP 72
#define KSBUF (64 * KP)

__global__ __launch_bounds__(256, 3) void attn_h_kernel()
{
    __shared__ __half Ks[2 * KSBUF];
    __shared__ unsigned Mb[2 * 256];

    const int b = blockIdx.z;
    const int h = blockIdx.y;
    const int q0 = blockIdx.x * 128;
    const int tid = threadIdx.x;
    const int w = tid >> 5;
    const int lane = tid & 31;
    const int g = lane >> 2;
    const int c = lane & 3;
    const unsigned ks0 = smem_u32(Ks);
    const unsigned mb0 = smem_u32(Mb);

    const __half* kbase = g_Kh + ((size_t)b * NN) * DD + h * KD;
    const unsigned* mbase = g_Mbits + (size_t)(b * NN + q0) * (NN / 32);

    const int str = tid >> 2;
    const int sseg = (tid & 3) * 16;
    const __half* ksrc = kbase + (size_t)str * DD + sseg;
    const unsigned kdst = ks0 + (str * KP + sseg) * 2;
    const unsigned* msrc = mbase + (size_t)(tid >> 1) * (NN / 32) + (tid & 1);
    const unsigned mdst = mb0 + tid * 4;

    cp16(kdst, ksrc);  cp16(kdst + 16, ksrc + 8);
    cp4(mdst, msrc);
    CP_COMMIT();

    const size_t qrow_g = (size_t)(b * NN + q0 + w * 16 + g);
    const __half* qr  = g_Qh + qrow_g * DD + h * KD;
    const __half* qr8 = qr + 8 * DD;
    unsigned aq[4][4];
#pragma unroll
    for (int kk = 0; kk < 4; kk++) {
        aq[kk][0] = *(const unsigned*)&qr [kk * 16 + 2 * c];
        aq[kk][1] = *(const unsigned*)&qr8[kk * 16 + 2 * c];
        aq[kk][2] = *(const unsigned*)&qr [kk * 16 + 8 + 2 * c];
        aq[kk][3] = *(const unsigned*)&qr8[kk * 16 + 8 + 2 * c];
    }

    float o[8][4];
#pragma unroll
    for (int i = 0; i < 8; i++)
#pragma unroll
        for (int j = 0; j < 4; j++) o[i][j] = 0.f;
    float l0 = 0.f, l1 = 0.f;

    const int lrow = lane & 15;
    const int lcol = (lane >> 4) * 8;

    for (int t = 0; t < NN / 64; t++) {
        const int buf = t & 1;
        if (t < NN / 64 - 1) {
            unsigned koff = (buf ^ 1) * KSBUF * 2;
            const __half* s = ksrc + (size_t)(t + 1) * 64 * DD;
            cp16(kdst + koff, s);  cp16(kdst + koff + 16, s + 8);
            cp4(mdst + (buf ^ 1) * 1024, msrc + (t + 1) * 2);
            CP_COMMIT();
            CP_WAIT1();
        } else {
            CP_WAIT0();
        }
        __syncthreads();

        const unsigned kb = ks0 + buf * KSBUF * 2;
        const unsigned* Mbb = Mb + buf * 256;
        const unsigned mg0 = Mbb[(w * 16 + g) * 2 + 0];
        const unsigned mg1 = Mbb[(w * 16 + g) * 2 + 1];
        const unsigned mh0 = Mbb[(w * 16 + g + 8) * 2 + 0];
        const unsigned mh1 = Mbb[(w * 16 + g + 8) * 2 + 1];

        unsigned ap[4][4];
#pragma unroll
        for (int j = 0; j < 4; j++) {
            float s0[4] = {0.f, 0.f, 0.f, 0.f};
            float s1[4] = {0.f, 0.f, 0.f, 0.f};
#pragma unroll
            for (int kk = 0; kk < 4; kk++) {
                unsigned r0, r1, r2, r3;
                unsigned a = kb + ((j * 16 + lrow) * KP + kk * 16 + lcol) * 2;
                ldsm_x4(r0, r1, r2, r3, a);
                mma_h(s0, aq[kk], r0, r2);
                mma_h(s1, aq[kk], r1, r3);
            }
            const int kb0 = j * 16 + 2 * c;
            const int kb1 = kb0 + 8;
            unsigned wg0 = (kb0 < 32) ? mg0 : mg1;
            unsigned wh0 = (kb0 < 32) ? mh0 : mh1;
            unsigned wg1 = (kb1 < 32) ? mg0 : mg1;
            unsigned wh1 = (kb1 < 32) ? mh0 : mh1;
            int sh0 = kb0 & 31, sh1 = kb1 & 31;

            float e00 = ((wg0 >> sh0) & 1u)       ? 0.f : ex2(s0[0]);
            float e01 = ((wg0 >> (sh0 + 1)) & 1u) ? 0.f : ex2(s0[1]);
            float e02 = ((wh0 >> sh0) & 1u)       ? 0.f : ex2(s0[2]);
            float e03 = ((wh0 >> (sh0 + 1)) & 1u) ? 0.f : ex2(s0[3]);
            float e10 = ((wg1 >> sh1) & 1u)       ? 0.f : ex2(s1[0]);
            float e11 = ((wg1 >> (sh1 + 1)) & 1u) ? 0.f : ex2(s1[1]);
            float e12 = ((wh1 >> sh1) & 1u)       ? 0.f : ex2(s1[2]);
            float e13 = ((wh1 >> (sh1 + 1)) & 1u) ? 0.f : ex2(s1[3]);

            l0 += (e00 + e01) + (e10 + e11);
            l1 += (e02 + e03) + (e12 + e13);

            ap[j][0] = packh2(e00, e01);
            ap[j][1] = packh2(e02, e03);
            ap[j][2] = packh2(e10, e11);
            ap[j][3] = packh2(e12, e13);
        }

#pragma unroll
        for (int j = 0; j < 4; j++) {
#pragma unroll
            for (int dn = 0; dn < 4; dn++) {
                unsigned r0, r1, r2, r3;
                unsigned a = kb + ((j * 16 + lrow) * KP + dn * 16 + lcol) * 2;
                ldsm_x4t(r0, r1, r2, r3, a);
                mma_h(o[2 * dn],     ap[j], r0, r1);
                mma_h(o[2 * dn + 1], ap[j], r2, r3);
            }
        }
        __syncthreads();
    }

    l0 += __shfl_xor_sync(0xFFFFFFFFu, l0, 1);
    l0 += __shfl_xor_sync(0xFFFFFFFFu, l0, 2);
    l1 += __shfl_xor_sync(0xFFFFFFFFu, l1, 1);
    l1 += __shfl_xor_sync(0xFFFFFFFFu, l1, 2);
    float inv0 = 1.f / l0;
    float inv1 = 1.f / l1;

    __half* og  = g_Oh + qrow_g * DD + h * KD;
    __half* og8 = og + 8 * DD;
#pragma unroll
    for (int nf = 0; nf < 8; nf++) {
        *(unsigned*)&og [nf * 8 + 2 * c] = packh2(o[nf][0] * inv0, o[nf][1] * inv0);
        *(unsigned*)&og8[nf * 8 + 2 * c] = packh2(o[nf][2] * inv1, o[nf][3] * inv1);
    }
}

// ---------------------------------------------------------------------------
// Launch
// ---------------------------------------------------------------------------
extern "C" void kernel_launch(void* const* d_in, const int* in_sizes, int n_in,
                              void* d_out, int out_size)
{
    const float* queries = (const float*)d_in[0];
    const unsigned char* mask = (const unsigned char*)d_in[1];
    const float* Wq = (const float*)d_in[2];
    const float* Wk = (const float*)d_in[3];
    const float* Wc = (const float*)d_in[4];
    float* out = (float*)d_out;

    __half *xh, *wqh, *wkh, *wch, *qh, *kh, *oh;
    cudaGetSymbolAddress((void**)&xh, g_Xh);
    cudaGetSymbolAddress((void**)&wqh, g_Wqh);
    cudaGetSymbolAddress((void**)&wkh, g_Wkh);
    cudaGetSymbolAddress((void**)&wch, g_Wch);
    cudaGetSymbolAddress((void**)&qh, g_Qh);
    cudaGetSymbolAddress((void**)&kh, g_Kh);
    cudaGetSymbolAddress((void**)&oh, g_Oh);

    // 0) conversions + mask prep
    detect_mask_kind<<<1, 256>>>((const unsigned int*)mask);
    mask_to_bits<<<(BB * NN * (NN / 32)) / 256, 256>>>(mask);
    conv_all_kernel<<<(int)((XELEMS + 3 * WELEMS) / 8 / 256), 256>>>(
        queries, Wq, Wk, Wc);

    // 1) Qh = Xh @ (QSCALE*Wq)^T, Kh = Xh @ Wk^T (fused via z)
    dim3 gproj(BB * NN / 128, DD / 128, 2);
    gemm_h_kernel<<<gproj, 256>>>(xh, wqh, wkh, qh, kh, 1);

    // 2) attention (16 q/warp, 3 blocks/SM target)
    dim3 gattn(NN / 128, HH, BB);
    attn_h_kernel<<<gattn, 256>>>();

    // 3) out = Oh @ Wc^T (fp32 out)
    dim3 gepi(BB * NN / 128, DD / 128, 1);
    gemm_h_kernel<<<gepi, 256>>>(oh, wch, wch, out, out, 0);
}

// round 12
// speedup vs baseline: 1.1198x; 1.1198x over previous
#include <cuda_runtime.h>
#include <cuda_fp16.h>
#include <math_constants.h>

// Problem constants
#define BB 4
#define NN 2048
#define DD 512
#define HH 8
#define KD 64
#define QSCALE 0.18033688011112042f   // (1/sqrt(64)) * log2(e)

// Scratch (static device globals -- no runtime allocation)
__device__ __half g_Xh[(size_t)BB * NN * DD];
__device__ __half g_Wqh[DD * DD];   // pre-scaled by QSCALE
__device__ __half g_Wkh[DD * DD];
__device__ __half g_Wch[DD * DD];
__device__ __half g_Qh[(size_t)BB * NN * DD];
__device__ __half g_Kh[(size_t)BB * NN * DD];
__device__ __half g_Oh[(size_t)BB * NN * DD];
__device__ unsigned int g_Mbits[(size_t)BB * NN * (NN / 32)];
__device__ int g_mask_is_byte;

// ---------------------------------------------------------------------------
// helpers
// ---------------------------------------------------------------------------
__device__ __forceinline__ unsigned smem_u32(const void* p)
{
    return (unsigned)__cvta_generic_to_shared(p);
}

__device__ __forceinline__ void cp16(unsigned d, const void* s)
{
    asm volatile("cp.async.ca.shared.global [%0], [%1], 16;" :: "r"(d), "l"(s));
}
__device__ __forceinline__ void cp4(unsigned d, const void* s)
{
    asm volatile("cp.async.ca.shared.global [%0], [%1], 4;" :: "r"(d), "l"(s));
}
#define CP_COMMIT() asm volatile("cp.async.commit_group;")
#define CP_WAIT1()  asm volatile("cp.async.wait_group 1;")
#define CP_WAIT0()  asm volatile("cp.async.wait_group 0;")

__device__ __forceinline__ void ldsm_x4(unsigned& r0, unsigned& r1,
                                        unsigned& r2, unsigned& r3, unsigned a)
{
    asm volatile("ldmatrix.sync.aligned.m8n8.x4.shared.b16 {%0,%1,%2,%3}, [%4];"
                 : "=r"(r0), "=r"(r1), "=r"(r2), "=r"(r3) : "r"(a));
}

__device__ __forceinline__ void ldsm_x4t(unsigned& r0, unsigned& r1,
                                         unsigned& r2, unsigned& r3, unsigned a)
{
    asm volatile("ldmatrix.sync.aligned.m8n8.x4.trans.shared.b16 {%0,%1,%2,%3}, [%4];"
                 : "=r"(r0), "=r"(r1), "=r"(r2), "=r"(r3) : "r"(a));
}

__device__ __forceinline__ void mma_h(float* c, const unsigned* a,
                                      unsigned b0, unsigned b1)
{
    asm volatile(
        "mma.sync.aligned.m16n8k16.row.col.f32.f16.f16.f32 "
        "{%0,%1,%2,%3},{%4,%5,%6,%7},{%8,%9},{%0,%1,%2,%3};"
        : "+f"(c[0]), "+f"(c[1]), "+f"(c[2]), "+f"(c[3])
        : "r"(a[0]), "r"(a[1]), "r"(a[2]), "r"(a[3]), "r"(b0), "r"(b1));
}

__device__ __forceinline__ float ex2(float x)
{
    float r;
    asm("ex2.approx.f32 %0, %1;" : "=f"(r) : "f"(x));
    return r;
}

__device__ __forceinline__ unsigned packh2(float a, float b)
{
    __half2 h = __floats2half2_rn(a, b);
    return *(unsigned*)&h;
}

// ---------------------------------------------------------------------------
// Mask dtype detection + bit compression
// ---------------------------------------------------------------------------
__global__ void detect_mask_kind(const unsigned int* __restrict__ m)
{
    __shared__ int s_byte;
    if (threadIdx.x == 0) s_byte = 0;
    __syncthreads();
    int local = 0;
    for (int i = threadIdx.x; i < 16384; i += blockDim.x) {
        unsigned int w = m[i];
        if (w != 0u && w != 1u && w != 0x3F800000u) local = 1;
    }
    if (local) s_byte = 1;
    __syncthreads();
    if (threadIdx.x == 0) g_mask_is_byte = s_byte;
}

__global__ void mask_to_bits(const unsigned char* __restrict__ mask)
{
    int idx = blockIdx.x * 256 + threadIdx.x;
    size_t row = (size_t)(idx >> 6);
    int w = idx & 63;
    unsigned int bits = 0;
    if (g_mask_is_byte) {
        const uint4* p = (const uint4*)(mask + row * NN + w * 32);
        uint4 A = p[0], Bv = p[1];
        unsigned int ws[8] = {A.x, A.y, A.z, A.w, Bv.x, Bv.y, Bv.z, Bv.w};
#pragma unroll
        for (int i = 0; i < 8; i++) {
            unsigned int v = ws[i];
            bits |= ((v >> 0)  & 1u) << (i * 4 + 0);
            bits |= ((v >> 8)  & 1u) << (i * 4 + 1);
            bits |= ((v >> 16) & 1u) << (i * 4 + 2);
            bits |= ((v >> 24) & 1u) << (i * 4 + 3);
        }
    } else {
        const uint4* p = (const uint4*)mask + row * (NN / 4) + w * 8;
#pragma unroll
        for (int i = 0; i < 8; i++) {
            uint4 t = p[i];
            bits |= (unsigned)(t.x != 0u) << (i * 4 + 0);
            bits |= (unsigned)(t.y != 0u) << (i * 4 + 1);
            bits |= (unsigned)(t.z != 0u) << (i * 4 + 2);
            bits |= (unsigned)(t.w != 0u) << (i * 4 + 3);
        }
    }
    g_Mbits[idx] = bits;
}

// ---------------------------------------------------------------------------
// fused fp32 -> fp16 conversion: covers X (4M elems) then Wq/Wk/Wc (256K each)
// ---------------------------------------------------------------------------
#define XELEMS ((size_t)BB * NN * DD)
#define WELEMS ((size_t)DD * DD)

__global__ void conv_all_kernel(const float* __restrict__ X,
                                const float* __restrict__ Wq,
                                const float* __restrict__ Wk,
                                const float* __restrict__ Wc)
{
    size_t i = ((size_t)blockIdx.x * 256 + threadIdx.x) * 8;
    const float* s;
    __half* d;
    float sc = 1.0f;
    if (i < XELEMS) {
        s = X + i;            d = g_Xh + i;
    } else if (i < XELEMS + WELEMS) {
        s = Wq + (i - XELEMS);            d = g_Wqh + (i - XELEMS);  sc = QSCALE;
    } else if (i < XELEMS + 2 * WELEMS) {
        s = Wk + (i - XELEMS - WELEMS);   d = g_Wkh + (i - XELEMS - WELEMS);
    } else {
        s = Wc + (i - XELEMS - 2 * WELEMS); d = g_Wch + (i - XELEMS - 2 * WELEMS);
    }
    float4 f0 = *(const float4*)s;
    float4 f1 = *(const float4*)(s + 4);
    *(uint4*)d = make_uint4(
        packh2(f0.x * sc, f0.y * sc), packh2(f0.z * sc, f0.w * sc),
        packh2(f1.x * sc, f1.y * sc), packh2(f1.z * sc, f1.w * sc));
}

// ---------------------------------------------------------------------------
// fp16 tensor-core GEMM, 3-stage cp.async pipeline.
// FIX vs round 11: last iteration uses CP_WAIT0 (tile t itself could still be
// in flight when no newer group exists to absorb the wait_group 1 slack).
// ---------------------------------------------------------------------------
#define GP 40
#define GBUF (128 * GP)
#define GT 16   // k-tiles

__global__ __launch_bounds__(256) void gemm_h_kernel(
    const __half* __restrict__ X,
    const __half* __restrict__ W0, const __half* __restrict__ W1,
    void* __restrict__ C0, void* __restrict__ C1, int out_half)
{
    __shared__ __half Xs[3 * GBUF];
    __shared__ __half Ws[3 * GBUF];

    const __half* __restrict__ W = (blockIdx.z == 0) ? W0 : W1;
    void* __restrict__ C = (blockIdx.z == 0) ? C0 : C1;

    const int bm = blockIdx.x * 128;
    const int bn = blockIdx.y * 128;
    const int tid = threadIdx.x;
    const int w = tid >> 5;
    const int lane = tid & 31;
    const int g = lane >> 2;
    const int c = lane & 3;
    const int wm = w & 3;
    const int wn = w >> 2;

    const unsigned xs0 = smem_u32(Xs);
    const unsigned ws0 = smem_u32(Ws);

    const int sr = tid >> 1;
    const int sg16 = (tid & 1) * 16;

    float acc[16][4];
#pragma unroll
    for (int i = 0; i < 16; i++)
#pragma unroll
        for (int j = 0; j < 4; j++) acc[i][j] = 0.f;

    const __half* xsrc = X + (size_t)(bm + sr) * 512 + sg16;
    const __half* wsrc = W + (size_t)(bn + sr) * 512 + sg16;
    const unsigned xdst = xs0 + (sr * GP + sg16) * 2;
    const unsigned wdst = ws0 + (sr * GP + sg16) * 2;

    // prologue: stage tiles 0 and 1 into slots 0 and 1
#pragma unroll
    for (int p = 0; p < 2; p++) {
        unsigned off = p * GBUF * 2;
        int k0 = p * 32;
        cp16(xdst + off, xsrc + k0);  cp16(xdst + off + 16, xsrc + k0 + 8);
        cp16(wdst + off, wsrc + k0);  cp16(wdst + off + 16, wsrc + k0 + 8);
        CP_COMMIT();
    }

    const int lrow = lane & 15;
    const int lcol = (lane >> 4) * 8;

    int slot = 0, slot2 = 2;
    for (int t = 0; t < GT; t++) {
        if (t < GT - 1) { CP_WAIT1(); } else { CP_WAIT0(); }
        __syncthreads();
        if (t + 2 < GT) {
            unsigned off = slot2 * GBUF * 2;
            int k0 = (t + 2) * 32;
            cp16(xdst + off, xsrc + k0);  cp16(xdst + off + 16, xsrc + k0 + 8);
            cp16(wdst + off, wsrc + k0);  cp16(wdst + off + 16, wsrc + k0 + 8);
            CP_COMMIT();
        }

        const unsigned xb = xs0 + slot * GBUF * 2;
        const unsigned wb = ws0 + slot * GBUF * 2;
#pragma unroll
        for (int kk = 0; kk < 2; kk++) {
            unsigned am[2][4];
#pragma unroll
            for (int mi = 0; mi < 2; mi++) {
                unsigned a = xb + ((wm * 32 + mi * 16 + lrow) * GP + kk * 16 + lcol) * 2;
                ldsm_x4(am[mi][0], am[mi][1], am[mi][2], am[mi][3], a);
            }
#pragma unroll
            for (int ng = 0; ng < 4; ng++) {
                unsigned r0, r1, r2, r3;
                unsigned a = wb + ((wn * 64 + ng * 16 + lrow) * GP + kk * 16 + lcol) * 2;
                ldsm_x4(r0, r1, r2, r3, a);
                mma_h(acc[0 * 8 + 2 * ng],     am[0], r0, r2);
                mma_h(acc[0 * 8 + 2 * ng + 1], am[0], r1, r3);
                mma_h(acc[1 * 8 + 2 * ng],     am[1], r0, r2);
                mma_h(acc[1 * 8 + 2 * ng + 1], am[1], r1, r3);
            }
        }
        slot = (slot == 2) ? 0 : slot + 1;
        slot2 = (slot2 == 2) ? 0 : slot2 + 1;
    }

#pragma unroll
    for (int mi = 0; mi < 2; mi++) {
#pragma unroll
        for (int nf = 0; nf < 8; nf++) {
            const float* a = acc[mi * 8 + nf];
            size_t grow = (size_t)(bm + wm * 32 + mi * 16 + g);
            int col = bn + wn * 64 + nf * 8 + 2 * c;
            if (out_half) {
                __half* Ch = (__half*)C;
                *(unsigned*)&Ch[grow * 512 + col]       = packh2(a[0], a[1]);
                *(unsigned*)&Ch[(grow + 8) * 512 + col] = packh2(a[2], a[3]);
            } else {
                float* Cf = (float*)C;
                *(float2*)&Cf[grow * 512 + col]       = make_float2(a[0], a[1]);
                *(float2*)&Cf[(grow + 8) * 512 + col] = make_float2(a[2], a[3]);
            }
        }
    }
}

// ---------------------------------------------------------------------------
// fp16 tensor-core flash attention (V = K), 3-stage cp.async pipeline,
// ONE syncthreads per key-tile. Last iteration uses CP_WAIT0 (race fix).
// ---------------------------------------------------------------------------
#define KP 72
#define KSBUF (64 * KP)
#define NT (NN / 64)   // 32 key tiles

__global__ __launch_bounds__(256) void attn_h_kernel()
{
    __shared__ __half Ks[3 * KSBUF];
    __shared__ unsigned Mb[3 * 256];

    const int b = blockIdx.z;
    const int h = blockIdx.y;
    const int q0 = blockIdx.x * 128;
    const int tid = threadIdx.x;
    const int w = tid >> 5;
    const int lane = tid & 31;
    const int g = lane >> 2;
    const int c = lane & 3;
    const unsigned ks0 = smem_u32(Ks);
    const unsigned mb0 = smem_u32(Mb);

    const __half* kbase = g_Kh + ((size_t)b * NN) * DD + h * KD;
    const unsigned* mbase = g_Mbits + (size_t)(b * NN + q0) * (NN / 32);

    const int str = tid >> 2;
    const int sseg = (tid & 3) * 16;
    const __half* ksrc = kbase + (size_t)str * DD + sseg;
    const unsigned kdst = ks0 + (str * KP + sseg) * 2;
    const unsigned* msrc = mbase + (size_t)(tid >> 1) * (NN / 32) + (tid & 1);
    const unsigned mdst = mb0 + tid * 4;

    // prologue: stage tiles 0 and 1
#pragma unroll
    for (int p = 0; p < 2; p++) {
        const __half* s = ksrc + (size_t)p * 64 * DD;
        unsigned off = p * KSBUF * 2;
        cp16(kdst + off, s);  cp16(kdst + off + 16, s + 8);
        cp4(mdst + p * 1024, msrc + p * 2);
        CP_COMMIT();
    }

    const size_t qrow_g = (size_t)(b * NN + q0 + w * 16 + g);
    const __half* qr  = g_Qh + qrow_g * DD + h * KD;
    const __half* qr8 = qr + 8 * DD;
    unsigned aq[4][4];
#pragma unroll
    for (int kk = 0; kk < 4; kk++) {
        aq[kk][0] = *(const unsigned*)&qr [kk * 16 + 2 * c];
        aq[kk][1] = *(const unsigned*)&qr8[kk * 16 + 2 * c];
        aq[kk][2] = *(const unsigned*)&qr [kk * 16 + 8 + 2 * c];
        aq[kk][3] = *(const unsigned*)&qr8[kk * 16 + 8 + 2 * c];
    }

    float o[8][4];
#pragma unroll
    for (int i = 0; i < 8; i++)
#pragma unroll
        for (int j = 0; j < 4; j++) o[i][j] = 0.f;
    float l0 = 0.f, l1 = 0.f;

    const int lrow = lane & 15;
    const int lcol = (lane >> 4) * 8;

    int slot = 0, slot2 = 2;
    for (int t = 0; t < NT; t++) {
        if (t < NT - 1) { CP_WAIT1(); } else { CP_WAIT0(); }
        __syncthreads();
        if (t + 2 < NT) {
            const __half* s = ksrc + (size_t)(t + 2) * 64 * DD;
            unsigned off = slot2 * KSBUF * 2;
            cp16(kdst + off, s);  cp16(kdst + off + 16, s + 8);
            cp4(mdst + slot2 * 1024, msrc + (t + 2) * 2);
            CP_COMMIT();
        }

        const unsigned kb = ks0 + slot * KSBUF * 2;
        const unsigned* Mbb = Mb + slot * 256;
        const unsigned mg0 = Mbb[(w * 16 + g) * 2 + 0];
        const unsigned mg1 = Mbb[(w * 16 + g) * 2 + 1];
        const unsigned mh0 = Mbb[(w * 16 + g + 8) * 2 + 0];
        const unsigned mh1 = Mbb[(w * 16 + g + 8) * 2 + 1];

        unsigned ap[4][4];
#pragma unroll
        for (int j = 0; j < 4; j++) {
            float s0[4] = {0.f, 0.f, 0.f, 0.f};
            float s1[4] = {0.f, 0.f, 0.f, 0.f};
#pragma unroll
            for (int kk = 0; kk < 4; kk++) {
                unsigned r0, r1, r2, r3;
                unsigned a = kb + ((j * 16 + lrow) * KP + kk * 16 + lcol) * 2;
                ldsm_x4(r0, r1, r2, r3, a);
                mma_h(s0, aq[kk], r0, r2);
                mma_h(s1, aq[kk], r1, r3);
            }
            const int kb0 = j * 16 + 2 * c;
            const int kb1 = kb0 + 8;
            unsigned wg0 = (kb0 < 32) ? mg0 : mg1;
            unsigned wh0 = (kb0 < 32) ? mh0 : mh1;
            unsigned wg1 = (kb1 < 32) ? mg0 : mg1;
            unsigned wh1 = (kb1 < 32) ? mh0 : mh1;
            int sh0 = kb0 & 31, sh1 = kb1 & 31;

            float e00 = ((wg0 >> sh0) & 1u)       ? 0.f : ex2(s0[0]);
            float e01 = ((wg0 >> (sh0 + 1)) & 1u) ? 0.f : ex2(s0[1]);
            float e02 = ((wh0 >> sh0) & 1u)       ? 0.f : ex2(s0[2]);
            float e03 = ((wh0 >> (sh0 + 1)) & 1u) ? 0.f : ex2(s0[3]);
            float e10 = ((wg1 >> sh1) & 1u)       ? 0.f : ex2(s1[0]);
            float e11 = ((wg1 >> (sh1 + 1)) & 1u) ? 0.f : ex2(s1[1]);
            float e12 = ((wh1 >> sh1) & 1u)       ? 0.f : ex2(s1[2]);
            float e13 = ((wh1 >> (sh1 + 1)) & 1u) ? 0.f : ex2(s1[3]);

            l0 += (e00 + e01) + (e10 + e11);
            l1 += (e02 + e03) + (e12 + e13);

            ap[j][0] = packh2(e00, e01);
            ap[j][1] = packh2(e02, e03);
            ap[j][2] = packh2(e10, e11);
            ap[j][3] = packh2(e12, e13);
        }

#pragma unroll
        for (int j = 0; j < 4; j++) {
#pragma unroll
            for (int dn = 0; dn < 4; dn++) {
                unsigned r0, r1, r2, r3;
                unsigned a = kb + ((j * 16 + lrow) * KP + dn * 16 + lcol) * 2;
                ldsm_x4t(r0, r1, r2, r3, a);
                mma_h(o[2 * dn],     ap[j], r0, r1);
                mma_h(o[2 * dn + 1], ap[j], r2, r3);
            }
        }
        slot = (slot == 2) ? 0 : slot + 1;
        slot2 = (slot2 == 2) ? 0 : slot2 + 1;
    }

    l0 += __shfl_xor_sync(0xFFFFFFFFu, l0, 1);
    l0 += __shfl_xor_sync(0xFFFFFFFFu, l0, 2);
    l1 += __shfl_xor_sync(0xFFFFFFFFu, l1, 1);
    l1 += __shfl_xor_sync(0xFFFFFFFFu, l1, 2);
    float inv0 = 1.f / l0;
    float inv1 = 1.f / l1;

    __half* og  = g_Oh + qrow_g * DD + h * KD;
    __half* og8 = og + 8 * DD;
#pragma unroll
    for (int nf = 0; nf < 8; nf++) {
        *(unsigned*)&og [nf * 8 + 2 * c] = packh2(o[nf][0] * inv0, o[nf][1] * inv0);
        *(unsigned*)&og8[nf * 8 + 2 * c] = packh2(o[nf][2] * inv1, o[nf][3] * inv1);
    }
}

// ---------------------------------------------------------------------------
// Launch
// ---------------------------------------------------------------------------
extern "C" void kernel_launch(void* const* d_in, const int* in_sizes, int n_in,
                              void* d_out, int out_size)
{
    const float* queries = (const float*)d_in[0];
    const unsigned char* mask = (const unsigned char*)d_in[1];
    const float* Wq = (const float*)d_in[2];
    const float* Wk = (const float*)d_in[3];
    const float* Wc = (const float*)d_in[4];
    float* out = (float*)d_out;

    __half *xh, *wqh, *wkh, *wch, *qh, *kh, *oh;
    cudaGetSymbolAddress((void**)&xh, g_Xh);
    cudaGetSymbolAddress((void**)&wqh, g_Wqh);
    cudaGetSymbolAddress((void**)&wkh, g_Wkh);
    cudaGetSymbolAddress((void**)&wch, g_Wch);
    cudaGetSymbolAddress((void**)&qh, g_Qh);
    cudaGetSymbolAddress((void**)&kh, g_Kh);
    cudaGetSymbolAddress((void**)&oh, g_Oh);

    // 0) conversions + mask prep
    detect_mask_kind<<<1, 256>>>((const unsigned int*)mask);
    mask_to_bits<<<(BB * NN * (NN / 32)) / 256, 256>>>(mask);
    conv_all_kernel<<<(int)((XELEMS + 3 * WELEMS) / 8 / 256), 256>>>(
        queries, Wq, Wk, Wc);

    // 1) Qh = Xh @ (QSCALE*Wq)^T, Kh = Xh @ Wk^T (fused via z)
    dim3 gproj(BB * NN / 128, DD / 128, 2);
    gemm_h_kernel<<<gproj, 256>>>(xh, wqh, wkh, qh, kh, 1);

    // 2) attention (3-stage pipeline, race-fixed)
    dim3 gattn(NN / 128, HH, BB);
    attn_h_kernel<<<gattn, 256>>>();

    // 3) out = Oh @ Wc^T (fp32 out)
    dim3 gepi(BB * NN / 128, DD / 128, 1);
    gemm_h_kernel<<<gepi, 256>>>(oh, wch, wch, out, out, 0);
}

// round 14
// speedup vs baseline: 1.1655x; 1.0408x over previous
#include <cuda_runtime.h>
#include <cuda_fp16.h>
#include <math_constants.h>

// Problem constants
#define BB 4
#define NN 2048
#define DD 512
#define HH 8
#define KD 64
#define QSCALE 0.18033688011112042f   // (1/sqrt(64)) * log2(e)

// Scratch (static device globals -- no runtime allocation)
__device__ __half g_Xh[(size_t)BB * NN * DD];
__device__ __half g_Wqh[DD * DD];   // pre-scaled by QSCALE
__device__ __half g_Wkh[DD * DD];
__device__ __half g_Wch[DD * DD];
__device__ __half g_Qh[(size_t)BB * NN * DD];
__device__ __half g_Kh[(size_t)BB * NN * DD];
__device__ __half g_Oh[(size_t)BB * NN * DD];
__device__ unsigned int g_Mbits[(size_t)BB * NN * (NN / 32)];
__device__ int g_mask_is_byte;

// ---------------------------------------------------------------------------
// helpers
// ---------------------------------------------------------------------------
__device__ __forceinline__ unsigned smem_u32(const void* p)
{
    return (unsigned)__cvta_generic_to_shared(p);
}

__device__ __forceinline__ void cp16(unsigned d, const void* s)
{
    asm volatile("cp.async.ca.shared.global [%0], [%1], 16;" :: "r"(d), "l"(s));
}
__device__ __forceinline__ void cp4(unsigned d, const void* s)
{
    asm volatile("cp.async.ca.shared.global [%0], [%1], 4;" :: "r"(d), "l"(s));
}
#define CP_COMMIT() asm volatile("cp.async.commit_group;")
#define CP_WAIT1()  asm volatile("cp.async.wait_group 1;")
#define CP_WAIT0()  asm volatile("cp.async.wait_group 0;")

__device__ __forceinline__ void ldsm_x4(unsigned& r0, unsigned& r1,
                                        unsigned& r2, unsigned& r3, unsigned a)
{
    asm volatile("ldmatrix.sync.aligned.m8n8.x4.shared.b16 {%0,%1,%2,%3}, [%4];"
                 : "=r"(r0), "=r"(r1), "=r"(r2), "=r"(r3) : "r"(a));
}

__device__ __forceinline__ void ldsm_x4t(unsigned& r0, unsigned& r1,
                                         unsigned& r2, unsigned& r3, unsigned a)
{
    asm volatile("ldmatrix.sync.aligned.m8n8.x4.trans.shared.b16 {%0,%1,%2,%3}, [%4];"
                 : "=r"(r0), "=r"(r1), "=r"(r2), "=r"(r3) : "r"(a));
}

__device__ __forceinline__ void mma_h(float* c, const unsigned* a,
                                      unsigned b0, unsigned b1)
{
    asm volatile(
        "mma.sync.aligned.m16n8k16.row.col.f32.f16.f16.f32 "
        "{%0,%1,%2,%3},{%4,%5,%6,%7},{%8,%9},{%0,%1,%2,%3};"
        : "+f"(c[0]), "+f"(c[1]), "+f"(c[2]), "+f"(c[3])
        : "r"(a[0]), "r"(a[1]), "r"(a[2]), "r"(a[3]), "r"(b0), "r"(b1));
}

__device__ __forceinline__ unsigned packh2(float a, float b)
{
    __half2 h = __floats2half2_rn(a, b);
    return *(unsigned*)&h;
}

// two exponentials (base 2) per MUFU op
__device__ __forceinline__ unsigned ex2_h2(unsigned x)
{
    unsigned r;
    asm("ex2.approx.f16x2 %0, %1;" : "=r"(r) : "r"(x));
    return r;
}

__device__ __forceinline__ unsigned hadd2u(unsigned a, unsigned b)
{
    unsigned r;
    asm("add.f16x2 %0, %1, %2;" : "=r"(r) : "r"(a), "r"(b));
    return r;
}

// ---------------------------------------------------------------------------
// Mask dtype detection + bit compression
// ---------------------------------------------------------------------------
__global__ void detect_mask_kind(const unsigned int* __restrict__ m)
{
    __shared__ int s_byte;
    if (threadIdx.x == 0) s_byte = 0;
    __syncthreads();
    int local = 0;
    for (int i = threadIdx.x; i < 16384; i += blockDim.x) {
        unsigned int w = m[i];
        if (w != 0u && w != 1u && w != 0x3F800000u) local = 1;
    }
    if (local) s_byte = 1;
    __syncthreads();
    if (threadIdx.x == 0) g_mask_is_byte = s_byte;
}

__global__ void mask_to_bits(const unsigned char* __restrict__ mask)
{
    int idx = blockIdx.x * 256 + threadIdx.x;
    size_t row = (size_t)(idx >> 6);
    int w = idx & 63;
    unsigned int bits = 0;
    if (g_mask_is_byte) {
        const uint4* p = (const uint4*)(mask + row * NN + w * 32);
        uint4 A = p[0], Bv = p[1];
        unsigned int ws[8] = {A.x, A.y, A.z, A.w, Bv.x, Bv.y, Bv.z, Bv.w};
#pragma unroll
        for (int i = 0; i < 8; i++) {
            unsigned int v = ws[i];
            bits |= ((v >> 0)  & 1u) << (i * 4 + 0);
            bits |= ((v >> 8)  & 1u) << (i * 4 + 1);
            bits |= ((v >> 16) & 1u) << (i * 4 + 2);
            bits |= ((v >> 24) & 1u) << (i * 4 + 3);
        }
    } else {
        const uint4* p = (const uint4*)mask + row * (NN / 4) + w * 8;
#pragma unroll
        for (int i = 0; i < 8; i++) {
            uint4 t = p[i];
            bits |= (unsigned)(t.x != 0u) << (i * 4 + 0);
            bits |= (unsigned)(t.y != 0u) << (i * 4 + 1);
            bits |= (unsigned)(t.z != 0u) << (i * 4 + 2);
            bits |= (unsigned)(t.w != 0u) << (i * 4 + 3);
        }
    }
    g_Mbits[idx] = bits;
}

// ---------------------------------------------------------------------------
// fused fp32 -> fp16 conversion: covers X (4M elems) then Wq/Wk/Wc (256K each)
// ---------------------------------------------------------------------------
#define XELEMS ((size_t)BB * NN * DD)
#define WELEMS ((size_t)DD * DD)

__global__ void conv_all_kernel(const float* __restrict__ X,
                                const float* __restrict__ Wq,
                                const float* __restrict__ Wk,
                                const float* __restrict__ Wc)
{
    size_t i = ((size_t)blockIdx.x * 256 + threadIdx.x) * 8;
    const float* s;
    __half* d;
    float sc = 1.0f;
    if (i < XELEMS) {
        s = X + i;            d = g_Xh + i;
    } else if (i < XELEMS + WELEMS) {
        s = Wq + (i - XELEMS);            d = g_Wqh + (i - XELEMS);  sc = QSCALE;
    } else if (i < XELEMS + 2 * WELEMS) {
        s = Wk + (i - XELEMS - WELEMS);   d = g_Wkh + (i - XELEMS - WELEMS);
    } else {
        s = Wc + (i - XELEMS - 2 * WELEMS); d = g_Wch + (i - XELEMS - 2 * WELEMS);
    }
    float4 f0 = *(const float4*)s;
    float4 f1 = *(const float4*)(s + 4);
    *(uint4*)d = make_uint4(
        packh2(f0.x * sc, f0.y * sc), packh2(f0.z * sc, f0.w * sc),
        packh2(f1.x * sc, f1.y * sc), packh2(f1.z * sc, f1.w * sc));
}

// ---------------------------------------------------------------------------
// fp16 tensor-core GEMM, 3-stage cp.async pipeline (round-12, passing).
// ---------------------------------------------------------------------------
#define GP 40
#define GBUF (128 * GP)
#define GT 16   // k-tiles

__global__ __launch_bounds__(256) void gemm_h_kernel(
    const __half* __restrict__ X,
    const __half* __restrict__ W0, const __half* __restrict__ W1,
    void* __restrict__ C0, void* __restrict__ C1, int out_half)
{
    __shared__ __half Xs[3 * GBUF];
    __shared__ __half Ws[3 * GBUF];

    const __half* __restrict__ W = (blockIdx.z == 0) ? W0 : W1;
    void* __restrict__ C = (blockIdx.z == 0) ? C0 : C1;

    const int bm = blockIdx.x * 128;
    const int bn = blockIdx.y * 128;
    const int tid = threadIdx.x;
    const int w = tid >> 5;
    const int lane = tid & 31;
    const int g = lane >> 2;
    const int c = lane & 3;
    const int wm = w & 3;
    const int wn = w >> 2;

    const unsigned xs0 = smem_u32(Xs);
    const unsigned ws0 = smem_u32(Ws);

    const int sr = tid >> 1;
    const int sg16 = (tid & 1) * 16;

    float acc[16][4];
#pragma unroll
    for (int i = 0; i < 16; i++)
#pragma unroll
        for (int j = 0; j < 4; j++) acc[i][j] = 0.f;

    const __half* xsrc = X + (size_t)(bm + sr) * 512 + sg16;
    const __half* wsrc = W + (size_t)(bn + sr) * 512 + sg16;
    const unsigned xdst = xs0 + (sr * GP + sg16) * 2;
    const unsigned wdst = ws0 + (sr * GP + sg16) * 2;

    // prologue: stage tiles 0 and 1 into slots 0 and 1
#pragma unroll
    for (int p = 0; p < 2; p++) {
        unsigned off = p * GBUF * 2;
        int k0 = p * 32;
        cp16(xdst + off, xsrc + k0);  cp16(xdst + off + 16, xsrc + k0 + 8);
        cp16(wdst + off, wsrc + k0);  cp16(wdst + off + 16, wsrc + k0 + 8);
        CP_COMMIT();
    }

    const int lrow = lane & 15;
    const int lcol = (lane >> 4) * 8;

    int slot = 0, slot2 = 2;
    for (int t = 0; t < GT; t++) {
        if (t < GT - 1) { CP_WAIT1(); } else { CP_WAIT0(); }
        __syncthreads();
        if (t + 2 < GT) {
            unsigned off = slot2 * GBUF * 2;
            int k0 = (t + 2) * 32;
            cp16(xdst + off, xsrc + k0);  cp16(xdst + off + 16, xsrc + k0 + 8);
            cp16(wdst + off, wsrc + k0);  cp16(wdst + off + 16, wsrc + k0 + 8);
            CP_COMMIT();
        }

        const unsigned xb = xs0 + slot * GBUF * 2;
        const unsigned wb = ws0 + slot * GBUF * 2;
#pragma unroll
        for (int kk = 0; kk < 2; kk++) {
            unsigned am[2][4];
#pragma unroll
            for (int mi = 0; mi < 2; mi++) {
                unsigned a = xb + ((wm * 32 + mi * 16 + lrow) * GP + kk * 16 + lcol) * 2;
                ldsm_x4(am[mi][0], am[mi][1], am[mi][2], am[mi][3], a);
            }
#pragma unroll
            for (int ng = 0; ng < 4; ng++) {
                unsigned r0, r1, r2, r3;
                unsigned a = wb + ((wn * 64 + ng * 16 + lrow) * GP + kk * 16 + lcol) * 2;
                ldsm_x4(r0, r1, r2, r3, a);
                mma_h(acc[0 * 8 + 2 * ng],     am[0], r0, r2);
                mma_h(acc[0 * 8 + 2 * ng + 1], am[0], r1, r3);
                mma_h(acc[1 * 8 + 2 * ng],     am[1], r0, r2);
                mma_h(acc[1 * 8 + 2 * ng + 1], am[1], r1, r3);
            }
        }
        slot = (slot == 2) ? 0 : slot + 1;
        slot2 = (slot2 == 2) ? 0 : slot2 + 1;
    }

#pragma unroll
    for (int mi = 0; mi < 2; mi++) {
#pragma unroll
        for (int nf = 0; nf < 8; nf++) {
            const float* a = acc[mi * 8 + nf];
            size_t grow = (size_t)(bm + wm * 32 + mi * 16 + g);
            int col = bn + wn * 64 + nf * 8 + 2 * c;
            if (out_half) {
                __half* Ch = (__half*)C;
                *(unsigned*)&Ch[grow * 512 + col]       = packh2(a[0], a[1]);
                *(unsigned*)&Ch[(grow + 8) * 512 + col] = packh2(a[2], a[3]);
            } else {
                float* Cf = (float*)C;
                *(float2*)&Cf[grow * 512 + col]       = make_float2(a[0], a[1]);
                *(float2*)&Cf[(grow + 8) * 512 + col] = make_float2(a[2], a[3]);
            }
        }
    }
}

// ---------------------------------------------------------------------------
// fp16 tensor-core flash attention (V = K), 3-stage cp.async pipeline.
// NEW vs round 12: softmax exp via ex2.approx.f16x2 (2 exps per MUFU op,
// halving MUFU occupancy); masking by AND-zero after exp; per-tile l
// accumulation in half2, folded to fp32 once per tile.
// ---------------------------------------------------------------------------
#define KP 72
#define KSBUF (64 * KP)
#define NT (NN / 64)   // 32 key tiles

__global__ __launch_bounds__(256) void attn_h_kernel()
{
    __shared__ __half Ks[3 * KSBUF];
    __shared__ unsigned Mb[3 * 256];

    const int b = blockIdx.z;
    const int h = blockIdx.y;
    const int q0 = blockIdx.x * 128;
    const int tid = threadIdx.x;
    const int w = tid >> 5;
    const int lane = tid & 31;
    const int g = lane >> 2;
    const int c = lane & 3;
    const unsigned ks0 = smem_u32(Ks);
    const unsigned mb0 = smem_u32(Mb);

    const __half* kbase = g_Kh + ((size_t)b * NN) * DD + h * KD;
    const unsigned* mbase = g_Mbits + (size_t)(b * NN + q0) * (NN / 32);

    const int str = tid >> 2;
    const int sseg = (tid & 3) * 16;
    const __half* ksrc = kbase + (size_t)str * DD + sseg;
    const unsigned kdst = ks0 + (str * KP + sseg) * 2;
    const unsigned* msrc = mbase + (size_t)(tid >> 1) * (NN / 32) + (tid & 1);
    const unsigned mdst = mb0 + tid * 4;

    // prologue: stage tiles 0 and 1
#pragma unroll
    for (int p = 0; p < 2; p++) {
        const __half* s = ksrc + (size_t)p * 64 * DD;
        unsigned off = p * KSBUF * 2;
        cp16(kdst + off, s);  cp16(kdst + off + 16, s + 8);
        cp4(mdst + p * 1024, msrc + p * 2);
        CP_COMMIT();
    }

    const size_t qrow_g = (size_t)(b * NN + q0 + w * 16 + g);
    const __half* qr  = g_Qh + qrow_g * DD + h * KD;
    const __half* qr8 = qr + 8 * DD;
    unsigned aq[4][4];
#pragma unroll
    for (int kk = 0; kk < 4; kk++) {
        aq[kk][0] = *(const unsigned*)&qr [kk * 16 + 2 * c];
        aq[kk][1] = *(const unsigned*)&qr8[kk * 16 + 2 * c];
        aq[kk][2] = *(const unsigned*)&qr [kk * 16 + 8 + 2 * c];
        aq[kk][3] = *(const unsigned*)&qr8[kk * 16 + 8 + 2 * c];
    }

    float o[8][4];
#pragma unroll
    for (int i = 0; i < 8; i++)
#pragma unroll
        for (int j = 0; j < 4; j++) o[i][j] = 0.f;
    float l0 = 0.f, l1 = 0.f;

    const int lrow = lane & 15;
    const int lcol = (lane >> 4) * 8;

    int slot = 0, slot2 = 2;
    for (int t = 0; t < NT; t++) {
        if (t < NT - 1) { CP_WAIT1(); } else { CP_WAIT0(); }
        __syncthreads();
        if (t + 2 < NT) {
            const __half* s = ksrc + (size_t)(t + 2) * 64 * DD;
            unsigned off = slot2 * KSBUF * 2;
            cp16(kdst + off, s);  cp16(kdst + off + 16, s + 8);
            cp4(mdst + slot2 * 1024, msrc + (t + 2) * 2);
            CP_COMMIT();
        }

        const unsigned kb = ks0 + slot * KSBUF * 2;
        const unsigned* Mbb = Mb + slot * 256;
        const unsigned mg0 = Mbb[(w * 16 + g) * 2 + 0];
        const unsigned mg1 = Mbb[(w * 16 + g) * 2 + 1];
        const unsigned mh0 = Mbb[(w * 16 + g + 8) * 2 + 0];
        const unsigned mh1 = Mbb[(w * 16 + g + 8) * 2 + 1];

        unsigned lh0 = 0, lh1 = 0;     // per-tile half2 row sums
        unsigned ap[4][4];
#pragma unroll
        for (int j = 0; j < 4; j++) {
            float s0[4] = {0.f, 0.f, 0.f, 0.f};
            float s1[4] = {0.f, 0.f, 0.f, 0.f};
#pragma unroll
            for (int kk = 0; kk < 4; kk++) {
                unsigned r0, r1, r2, r3;
                unsigned a = kb + ((j * 16 + lrow) * KP + kk * 16 + lcol) * 2;
                ldsm_x4(r0, r1, r2, r3, a);
                mma_h(s0, aq[kk], r0, r2);
                mma_h(s1, aq[kk], r1, r3);
            }
            const int kb0 = j * 16 + 2 * c;
            const int kb1 = kb0 + 8;
            unsigned wg0 = (kb0 < 32) ? mg0 : mg1;
            unsigned wh0 = (kb0 < 32) ? mh0 : mh1;
            unsigned wg1 = (kb1 < 32) ? mg0 : mg1;
            unsigned wh1 = (kb1 < 32) ? mh0 : mh1;
            int sh0 = kb0 & 31, sh1 = kb1 & 31;

            // pack score pairs to f16x2, exponentiate 2-at-a-time on MUFU
            unsigned e00 = ex2_h2(packh2(s0[0], s0[1]));   // row g,   keys kb0..+1
            unsigned e01 = ex2_h2(packh2(s0[2], s0[3]));   // row g+8, keys kb0..+1
            unsigned e10 = ex2_h2(packh2(s1[0], s1[1]));   // row g,   keys kb1..+1
            unsigned e11 = ex2_h2(packh2(s1[2], s1[3]));   // row g+8, keys kb1..+1

            // mask: AND-zero the masked half lanes
            unsigned b2;
            b2 = (wg0 >> sh0) & 3u;
            e00 &= ((b2 & 1u) ? 0u : 0xFFFFu) | ((b2 & 2u) ? 0u : 0xFFFF0000u);
            b2 = (wh0 >> sh0) & 3u;
            e01 &= ((b2 & 1u) ? 0u : 0xFFFFu) | ((b2 & 2u) ? 0u : 0xFFFF0000u);
            b2 = (wg1 >> sh1) & 3u;
            e10 &= ((b2 & 1u) ? 0u : 0xFFFFu) | ((b2 & 2u) ? 0u : 0xFFFF0000u);
            b2 = (wh1 >> sh1) & 3u;
            e11 &= ((b2 & 1u) ? 0u : 0xFFFFu) | ((b2 & 2u) ? 0u : 0xFFFF0000u);

            lh0 = hadd2u(lh0, hadd2u(e00, e10));
            lh1 = hadd2u(lh1, hadd2u(e01, e11));

            ap[j][0] = e00;
            ap[j][1] = e01;
            ap[j][2] = e10;
            ap[j][3] = e11;
        }

        // fold per-tile half2 sums into fp32
        {
            __half2 t0 = *(__half2*)&lh0;
            __half2 t1 = *(__half2*)&lh1;
            l0 += __low2float(t0) + __high2float(t0);
            l1 += __low2float(t1) + __high2float(t1);
        }

#pragma unroll
        for (int j = 0; j < 4; j++) {
#pragma unroll
            for (int dn = 0; dn < 4; dn++) {
                unsigned r0, r1, r2, r3;
                unsigned a = kb + ((j * 16 + lrow) * KP + dn * 16 + lcol) * 2;
                ldsm_x4t(r0, r1, r2, r3, a);
                mma_h(o[2 * dn],     ap[j], r0, r1);
                mma_h(o[2 * dn + 1], ap[j], r2, r3);
            }
        }
        slot = (slot == 2) ? 0 : slot + 1;
        slot2 = (slot2 == 2) ? 0 : slot2 + 1;
    }

    l0 += __shfl_xor_sync(0xFFFFFFFFu, l0, 1);
    l0 += __shfl_xor_sync(0xFFFFFFFFu, l0, 2);
    l1 += __shfl_xor_sync(0xFFFFFFFFu, l1, 1);
    l1 += __shfl_xor_sync(0xFFFFFFFFu, l1, 2);
    float inv0 = 1.f / l0;
    float inv1 = 1.f / l1;

    __half* og  = g_Oh + qrow_g * DD + h * KD;
    __half* og8 = og + 8 * DD;
#pragma unroll
    for (int nf = 0; nf < 8; nf++) {
        *(unsigned*)&og [nf * 8 + 2 * c] = packh2(o[nf][0] * inv0, o[nf][1] * inv0);
        *(unsigned*)&og8[nf * 8 + 2 * c] = packh2(o[nf][2] * inv1, o[nf][3] * inv1);
    }
}

// ---------------------------------------------------------------------------
// Launch
// ---------------------------------------------------------------------------
extern "C" void kernel_launch(void* const* d_in, const int* in_sizes, int n_in,
                              void* d_out, int out_size)
{
    const float* queries = (const float*)d_in[0];
    const unsigned char* mask = (const unsigned char*)d_in[1];
    const float* Wq = (const float*)d_in[2];
    const float* Wk = (const float*)d_in[3];
    const float* Wc = (const float*)d_in[4];
    float* out = (float*)d_out;

    __half *xh, *wqh, *wkh, *wch, *qh, *kh, *oh;
    cudaGetSymbolAddress((void**)&xh, g_Xh);
    cudaGetSymbolAddress((void**)&wqh, g_Wqh);
    cudaGetSymbolAddress((void**)&wkh, g_Wkh);
    cudaGetSymbolAddress((void**)&wch, g_Wch);
    cudaGetSymbolAddress((void**)&qh, g_Qh);
    cudaGetSymbolAddress((void**)&kh, g_Kh);
    cudaGetSymbolAddress((void**)&oh, g_Oh);

    // 0) conversions + mask prep
    detect_mask_kind<<<1, 256>>>((const unsigned int*)mask);
    mask_to_bits<<<(BB * NN * (NN / 32)) / 256, 256>>>(mask);
    conv_all_kernel<<<(int)((XELEMS + 3 * WELEMS) / 8 / 256), 256>>>(
        queries, Wq, Wk, Wc);

    // 1) Qh = Xh @ (QSCALE*Wq)^T, Kh = Xh @ Wk^T (fused via z)
    dim3 gproj(BB * NN / 128, DD / 128, 2);
    gemm_h_kernel<<<gproj, 256>>>(xh, wqh, wkh, qh, kh, 1);

    // 2) attention (f16x2 exp path)
    dim3 gattn(NN / 128, HH, BB);
    attn_h_kernel<<<gattn, 256>>>();

    // 3) out = Oh @ Wc^T (fp32 out)
    dim3 gepi(BB * NN / 128, DD / 128, 1);
    gemm_h_kernel<<<gepi, 256>>>(oh, wch, wch, out, out, 0);
}

// round 15
// speedup vs baseline: 1.1958x; 1.0260x over previous
#include <cuda_runtime.h>
#include <cuda_fp16.h>
#include <math_constants.h>

// Problem constants
#define BB 4
#define NN 2048
#define DD 512
#define HH 8
#define KD 64
#define QSCALE 0.18033688011112042f   // (1/sqrt(64)) * log2(e)

// Scratch (static device globals -- no runtime allocation)
__device__ __half g_Xh[(size_t)BB * NN * DD];
__device__ __half g_Wqh[DD * DD];   // pre-scaled by QSCALE
__device__ __half g_Wkh[DD * DD];
__device__ __half g_Wch[DD * DD];
__device__ __half g_Qh[(size_t)BB * NN * DD];
__device__ __half g_Kh[(size_t)BB * NN * DD];
__device__ __half g_Oh[(size_t)BB * NN * DD];
__device__ unsigned int g_Mbits[(size_t)BB * NN * (NN / 32)];
__device__ int g_mask_is_byte;

// ---------------------------------------------------------------------------
// helpers
// ---------------------------------------------------------------------------
__device__ __forceinline__ unsigned smem_u32(const void* p)
{
    return (unsigned)__cvta_generic_to_shared(p);
}

__device__ __forceinline__ void cp16(unsigned d, const void* s)
{
    asm volatile("cp.async.ca.shared.global [%0], [%1], 16;" :: "r"(d), "l"(s));
}
__device__ __forceinline__ void cp4(unsigned d, const void* s)
{
    asm volatile("cp.async.ca.shared.global [%0], [%1], 4;" :: "r"(d), "l"(s));
}
#define CP_COMMIT() asm volatile("cp.async.commit_group;")
#define CP_WAIT1()  asm volatile("cp.async.wait_group 1;")
#define CP_WAIT0()  asm volatile("cp.async.wait_group 0;")

__device__ __forceinline__ void ldsm_x4(unsigned& r0, unsigned& r1,
                                        unsigned& r2, unsigned& r3, unsigned a)
{
    asm volatile("ldmatrix.sync.aligned.m8n8.x4.shared.b16 {%0,%1,%2,%3}, [%4];"
                 : "=r"(r0), "=r"(r1), "=r"(r2), "=r"(r3) : "r"(a));
}

__device__ __forceinline__ void ldsm_x4t(unsigned& r0, unsigned& r1,
                                         unsigned& r2, unsigned& r3, unsigned a)
{
    asm volatile("ldmatrix.sync.aligned.m8n8.x4.trans.shared.b16 {%0,%1,%2,%3}, [%4];"
                 : "=r"(r0), "=r"(r1), "=r"(r2), "=r"(r3) : "r"(a));
}

__device__ __forceinline__ void mma_h(float* c, const unsigned* a,
                                      unsigned b0, unsigned b1)
{
    asm volatile(
        "mma.sync.aligned.m16n8k16.row.col.f32.f16.f16.f32 "
        "{%0,%1,%2,%3},{%4,%5,%6,%7},{%8,%9},{%0,%1,%2,%3};"
        : "+f"(c[0]), "+f"(c[1]), "+f"(c[2]), "+f"(c[3])
        : "r"(a[0]), "r"(a[1]), "r"(a[2]), "r"(a[3]), "r"(b0), "r"(b1));
}

__device__ __forceinline__ unsigned packh2(float a, float b)
{
    __half2 h = __floats2half2_rn(a, b);
    return *(unsigned*)&h;
}

// two exponentials (base 2) per MUFU op
__device__ __forceinline__ unsigned ex2_h2(unsigned x)
{
    unsigned r;
    asm("ex2.approx.f16x2 %0, %1;" : "=r"(r) : "r"(x));
    return r;
}

__device__ __forceinline__ unsigned hadd2u(unsigned a, unsigned b)
{
    unsigned r;
    asm("add.f16x2 %0, %1, %2;" : "=r"(r) : "r"(a), "r"(b));
    return r;
}

// ---------------------------------------------------------------------------
// Mask dtype detection + bit compression
// ---------------------------------------------------------------------------
__global__ void detect_mask_kind(const unsigned int* __restrict__ m)
{
    __shared__ int s_byte;
    if (threadIdx.x == 0) s_byte = 0;
    __syncthreads();
    int local = 0;
    for (int i = threadIdx.x; i < 16384; i += blockDim.x) {
        unsigned int w = m[i];
        if (w != 0u && w != 1u && w != 0x3F800000u) local = 1;
    }
    if (local) s_byte = 1;
    __syncthreads();
    if (threadIdx.x == 0) g_mask_is_byte = s_byte;
}

__global__ void mask_to_bits(const unsigned char* __restrict__ mask)
{
    int idx = blockIdx.x * 256 + threadIdx.x;
    size_t row = (size_t)(idx >> 6);
    int w = idx & 63;
    unsigned int bits = 0;
    if (g_mask_is_byte) {
        const uint4* p = (const uint4*)(mask + row * NN + w * 32);
        uint4 A = p[0], Bv = p[1];
        unsigned int ws[8] = {A.x, A.y, A.z, A.w, Bv.x, Bv.y, Bv.z, Bv.w};
#pragma unroll
        for (int i = 0; i < 8; i++) {
            unsigned int v = ws[i];
            bits |= ((v >> 0)  & 1u) << (i * 4 + 0);
            bits |= ((v >> 8)  & 1u) << (i * 4 + 1);
            bits |= ((v >> 16) & 1u) << (i * 4 + 2);
            bits |= ((v >> 24) & 1u) << (i * 4 + 3);
        }
    } else {
        const uint4* p = (const uint4*)mask + row * (NN / 4) + w * 8;
#pragma unroll
        for (int i = 0; i < 8; i++) {
            uint4 t = p[i];
            bits |= (unsigned)(t.x != 0u) << (i * 4 + 0);
            bits |= (unsigned)(t.y != 0u) << (i * 4 + 1);
            bits |= (unsigned)(t.z != 0u) << (i * 4 + 2);
            bits |= (unsigned)(t.w != 0u) << (i * 4 + 3);
        }
    }
    g_Mbits[idx] = bits;
}

// ---------------------------------------------------------------------------
// fused fp32 -> fp16 conversion: covers X (4M elems) then Wq/Wk/Wc (256K each)
// ---------------------------------------------------------------------------
#define XELEMS ((size_t)BB * NN * DD)
#define WELEMS ((size_t)DD * DD)

__global__ void conv_all_kernel(const float* __restrict__ X,
                                const float* __restrict__ Wq,
                                const float* __restrict__ Wk,
                                const float* __restrict__ Wc)
{
    size_t i = ((size_t)blockIdx.x * 256 + threadIdx.x) * 8;
    const float* s;
    __half* d;
    float sc = 1.0f;
    if (i < XELEMS) {
        s = X + i;            d = g_Xh + i;
    } else if (i < XELEMS + WELEMS) {
        s = Wq + (i - XELEMS);            d = g_Wqh + (i - XELEMS);  sc = QSCALE;
    } else if (i < XELEMS + 2 * WELEMS) {
        s = Wk + (i - XELEMS - WELEMS);   d = g_Wkh + (i - XELEMS - WELEMS);
    } else {
        s = Wc + (i - XELEMS - 2 * WELEMS); d = g_Wch + (i - XELEMS - 2 * WELEMS);
    }
    float4 f0 = *(const float4*)s;
    float4 f1 = *(const float4*)(s + 4);
    *(uint4*)d = make_uint4(
        packh2(f0.x * sc, f0.y * sc), packh2(f0.z * sc, f0.w * sc),
        packh2(f1.x * sc, f1.y * sc), packh2(f1.z * sc, f1.w * sc));
}

// ---------------------------------------------------------------------------
// fp16 tensor-core GEMM, 3-stage cp.async pipeline (round-12, passing).
// ---------------------------------------------------------------------------
#define GP 40
#define GBUF (128 * GP)
#define GT 16   // k-tiles

__global__ __launch_bounds__(256) void gemm_h_kernel(
    const __half* __restrict__ X,
    const __half* __restrict__ W0, const __half* __restrict__ W1,
    void* __restrict__ C0, void* __restrict__ C1, int out_half)
{
    __shared__ __half Xs[3 * GBUF];
    __shared__ __half Ws[3 * GBUF];

    const __half* __restrict__ W = (blockIdx.z == 0) ? W0 : W1;
    void* __restrict__ C = (blockIdx.z == 0) ? C0 : C1;

    const int bm = blockIdx.x * 128;
    const int bn = blockIdx.y * 128;
    const int tid = threadIdx.x;
    const int w = tid >> 5;
    const int lane = tid & 31;
    const int g = lane >> 2;
    const int c = lane & 3;
    const int wm = w & 3;
    const int wn = w >> 2;

    const unsigned xs0 = smem_u32(Xs);
    const unsigned ws0 = smem_u32(Ws);

    const int sr = tid >> 1;
    const int sg16 = (tid & 1) * 16;

    float acc[16][4];
#pragma unroll
    for (int i = 0; i < 16; i++)
#pragma unroll
        for (int j = 0; j < 4; j++) acc[i][j] = 0.f;

    const __half* xsrc = X + (size_t)(bm + sr) * 512 + sg16;
    const __half* wsrc = W + (size_t)(bn + sr) * 512 + sg16;
    const unsigned xdst = xs0 + (sr * GP + sg16) * 2;
    const unsigned wdst = ws0 + (sr * GP + sg16) * 2;

    // prologue: stage tiles 0 and 1 into slots 0 and 1
#pragma unroll
    for (int p = 0; p < 2; p++) {
        unsigned off = p * GBUF * 2;
        int k0 = p * 32;
        cp16(xdst + off, xsrc + k0);  cp16(xdst + off + 16, xsrc + k0 + 8);
        cp16(wdst + off, wsrc + k0);  cp16(wdst + off + 16, wsrc + k0 + 8);
        CP_COMMIT();
    }

    const int lrow = lane & 15;
    const int lcol = (lane >> 4) * 8;

    int slot = 0, slot2 = 2;
    for (int t = 0; t < GT; t++) {
        if (t < GT - 1) { CP_WAIT1(); } else { CP_WAIT0(); }
        __syncthreads();
        if (t + 2 < GT) {
            unsigned off = slot2 * GBUF * 2;
            int k0 = (t + 2) * 32;
            cp16(xdst + off, xsrc + k0);  cp16(xdst + off + 16, xsrc + k0 + 8);
            cp16(wdst + off, wsrc + k0);  cp16(wdst + off + 16, wsrc + k0 + 8);
            CP_COMMIT();
        }

        const unsigned xb = xs0 + slot * GBUF * 2;
        const unsigned wb = ws0 + slot * GBUF * 2;
#pragma unroll
        for (int kk = 0; kk < 2; kk++) {
            unsigned am[2][4];
#pragma unroll
            for (int mi = 0; mi < 2; mi++) {
                unsigned a = xb + ((wm * 32 + mi * 16 + lrow) * GP + kk * 16 + lcol) * 2;
                ldsm_x4(am[mi][0], am[mi][1], am[mi][2], am[mi][3], a);
            }
#pragma unroll
            for (int ng = 0; ng < 4; ng++) {
                unsigned r0, r1, r2, r3;
                unsigned a = wb + ((wn * 64 + ng * 16 + lrow) * GP + kk * 16 + lcol) * 2;
                ldsm_x4(r0, r1, r2, r3, a);
                mma_h(acc[0 * 8 + 2 * ng],     am[0], r0, r2);
                mma_h(acc[0 * 8 + 2 * ng + 1], am[0], r1, r3);
                mma_h(acc[1 * 8 + 2 * ng],     am[1], r0, r2);
                mma_h(acc[1 * 8 + 2 * ng + 1], am[1], r1, r3);
            }
        }
        slot = (slot == 2) ? 0 : slot + 1;
        slot2 = (slot2 == 2) ? 0 : slot2 + 1;
    }

#pragma unroll
    for (int mi = 0; mi < 2; mi++) {
#pragma unroll
        for (int nf = 0; nf < 8; nf++) {
            const float* a = acc[mi * 8 + nf];
            size_t grow = (size_t)(bm + wm * 32 + mi * 16 + g);
            int col = bn + wn * 64 + nf * 8 + 2 * c;
            if (out_half) {
                __half* Ch = (__half*)C;
                *(unsigned*)&Ch[grow * 512 + col]       = packh2(a[0], a[1]);
                *(unsigned*)&Ch[(grow + 8) * 512 + col] = packh2(a[2], a[3]);
            } else {
                float* Cf = (float*)C;
                *(float2*)&Cf[grow * 512 + col]       = make_float2(a[0], a[1]);
                *(float2*)&Cf[(grow + 8) * 512 + col] = make_float2(a[2], a[3]);
            }
        }
    }
}

// ---------------------------------------------------------------------------
// fp16 tensor-core flash attention (V = K), 3-stage cp.async pipeline,
// f16x2 exp path. NEW vs round 14: 128-thread blocks (4 warps x 16 q = 64 q)
// targeting 5 blocks/SM (20 warps) via __launch_bounds__(128, 5); warp-level
// structure unchanged (best measured).
// ---------------------------------------------------------------------------
#define KP 72
#define KSBUF (64 * KP)
#define NT (NN / 64)   // 32 key tiles

__global__ __launch_bounds__(128, 5) void attn_h_kernel()
{
    __shared__ __half Ks[3 * KSBUF];
    __shared__ unsigned Mb[3 * 128];      // 64 q rows x 2 words per stage

    const int b = blockIdx.z;
    const int h = blockIdx.y;
    const int q0 = blockIdx.x * 64;
    const int tid = threadIdx.x;
    const int w = tid >> 5;               // warp 0..3
    const int lane = tid & 31;
    const int g = lane >> 2;
    const int c = lane & 3;
    const unsigned ks0 = smem_u32(Ks);
    const unsigned mb0 = smem_u32(Mb);

    const __half* kbase = g_Kh + ((size_t)b * NN) * DD + h * KD;
    const unsigned* mbase = g_Mbits + (size_t)(b * NN + q0) * (NN / 32);

    // K staging: 64 rows x 128B; 2 threads per row, 64B (4 cp16) each
    const int str = tid >> 1;
    const int sseg = (tid & 1) * 32;      // halves
    const __half* ksrc = kbase + (size_t)str * DD + sseg;
    const unsigned kdst = ks0 + (str * KP + sseg) * 2;
    // mask staging: 64 rows x 2 words = 128 words; 1 word per thread
    const unsigned* msrc = mbase + (size_t)(tid >> 1) * (NN / 32) + (tid & 1);
    const unsigned mdst = mb0 + tid * 4;

    // prologue: stage tiles 0 and 1
#pragma unroll
    for (int p = 0; p < 2; p++) {
        const __half* s = ksrc + (size_t)p * 64 * DD;
        unsigned off = p * KSBUF * 2;
        cp16(kdst + off, s);       cp16(kdst + off + 16, s + 8);
        cp16(kdst + off + 32, s + 16);  cp16(kdst + off + 48, s + 24);
        cp4(mdst + p * 512, msrc + p * 2);
        CP_COMMIT();
    }

    const size_t qrow_g = (size_t)(b * NN + q0 + w * 16 + g);
    const __half* qr  = g_Qh + qrow_g * DD + h * KD;
    const __half* qr8 = qr + 8 * DD;
    unsigned aq[4][4];
#pragma unroll
    for (int kk = 0; kk < 4; kk++) {
        aq[kk][0] = *(const unsigned*)&qr [kk * 16 + 2 * c];
        aq[kk][1] = *(const unsigned*)&qr8[kk * 16 + 2 * c];
        aq[kk][2] = *(const unsigned*)&qr [kk * 16 + 8 + 2 * c];
        aq[kk][3] = *(const unsigned*)&qr8[kk * 16 + 8 + 2 * c];
    }

    float o[8][4];
#pragma unroll
    for (int i = 0; i < 8; i++)
#pragma unroll
        for (int j = 0; j < 4; j++) o[i][j] = 0.f;
    float l0 = 0.f, l1 = 0.f;

    const int lrow = lane & 15;
    const int lcol = (lane >> 4) * 8;

    int slot = 0, slot2 = 2;
    for (int t = 0; t < NT; t++) {
        if (t < NT - 1) { CP_WAIT1(); } else { CP_WAIT0(); }
        __syncthreads();
        if (t + 2 < NT) {
            const __half* s = ksrc + (size_t)(t + 2) * 64 * DD;
            unsigned off = slot2 * KSBUF * 2;
            cp16(kdst + off, s);       cp16(kdst + off + 16, s + 8);
            cp16(kdst + off + 32, s + 16);  cp16(kdst + off + 48, s + 24);
            cp4(mdst + slot2 * 512, msrc + (t + 2) * 2);
            CP_COMMIT();
        }

        const unsigned kb = ks0 + slot * KSBUF * 2;
        const unsigned* Mbb = Mb + slot * 128;
        const unsigned mg0 = Mbb[(w * 16 + g) * 2 + 0];
        const unsigned mg1 = Mbb[(w * 16 + g) * 2 + 1];
        const unsigned mh0 = Mbb[(w * 16 + g + 8) * 2 + 0];
        const unsigned mh1 = Mbb[(w * 16 + g + 8) * 2 + 1];

        unsigned lh0 = 0, lh1 = 0;     // per-tile half2 row sums
        unsigned ap[4][4];
#pragma unroll
        for (int j = 0; j < 4; j++) {
            float s0[4] = {0.f, 0.f, 0.f, 0.f};
            float s1[4] = {0.f, 0.f, 0.f, 0.f};
#pragma unroll
            for (int kk = 0; kk < 4; kk++) {
                unsigned r0, r1, r2, r3;
                unsigned a = kb + ((j * 16 + lrow) * KP + kk * 16 + lcol) * 2;
                ldsm_x4(r0, r1, r2, r3, a);
                mma_h(s0, aq[kk], r0, r2);
                mma_h(s1, aq[kk], r1, r3);
            }
            const int kb0 = j * 16 + 2 * c;
            const int kb1 = kb0 + 8;
            unsigned wg0 = (kb0 < 32) ? mg0 : mg1;
            unsigned wh0 = (kb0 < 32) ? mh0 : mh1;
            unsigned wg1 = (kb1 < 32) ? mg0 : mg1;
            unsigned wh1 = (kb1 < 32) ? mh0 : mh1;
            int sh0 = kb0 & 31, sh1 = kb1 & 31;

            unsigned e00 = ex2_h2(packh2(s0[0], s0[1]));
            unsigned e01 = ex2_h2(packh2(s0[2], s0[3]));
            unsigned e10 = ex2_h2(packh2(s1[0], s1[1]));
            unsigned e11 = ex2_h2(packh2(s1[2], s1[3]));

            unsigned b2;
            b2 = (wg0 >> sh0) & 3u;
            e00 &= ((b2 & 1u) ? 0u : 0xFFFFu) | ((b2 & 2u) ? 0u : 0xFFFF0000u);
            b2 = (wh0 >> sh0) & 3u;
            e01 &= ((b2 & 1u) ? 0u : 0xFFFFu) | ((b2 & 2u) ? 0u : 0xFFFF0000u);
            b2 = (wg1 >> sh1) & 3u;
            e10 &= ((b2 & 1u) ? 0u : 0xFFFFu) | ((b2 & 2u) ? 0u : 0xFFFF0000u);
            b2 = (wh1 >> sh1) & 3u;
            e11 &= ((b2 & 1u) ? 0u : 0xFFFFu) | ((b2 & 2u) ? 0u : 0xFFFF0000u);

            lh0 = hadd2u(lh0, hadd2u(e00, e10));
            lh1 = hadd2u(lh1, hadd2u(e01, e11));

            ap[j][0] = e00;
            ap[j][1] = e01;
            ap[j][2] = e10;
            ap[j][3] = e11;
        }

        {
            __half2 t0 = *(__half2*)&lh0;
            __half2 t1 = *(__half2*)&lh1;
            l0 += __low2float(t0) + __high2float(t0);
            l1 += __low2float(t1) + __high2float(t1);
        }

#pragma unroll
        for (int j = 0; j < 4; j++) {
#pragma unroll
            for (int dn = 0; dn < 4; dn++) {
                unsigned r0, r1, r2, r3;
                unsigned a = kb + ((j * 16 + lrow) * KP + dn * 16 + lcol) * 2;
                ldsm_x4t(r0, r1, r2, r3, a);
                mma_h(o[2 * dn],     ap[j], r0, r1);
                mma_h(o[2 * dn + 1], ap[j], r2, r3);
            }
        }
        slot = (slot == 2) ? 0 : slot + 1;
        slot2 = (slot2 == 2) ? 0 : slot2 + 1;
    }

    l0 += __shfl_xor_sync(0xFFFFFFFFu, l0, 1);
    l0 += __shfl_xor_sync(0xFFFFFFFFu, l0, 2);
    l1 += __shfl_xor_sync(0xFFFFFFFFu, l1, 1);
    l1 += __shfl_xor_sync(0xFFFFFFFFu, l1, 2);
    float inv0 = 1.f / l0;
    float inv1 = 1.f / l1;

    __half* og  = g_Oh + qrow_g * DD + h * KD;
    __half* og8 = og + 8 * DD;
#pragma unroll
    for (int nf = 0; nf < 8; nf++) {
        *(unsigned*)&og [nf * 8 + 2 * c] = packh2(o[nf][0] * inv0, o[nf][1] * inv0);
        *(unsigned*)&og8[nf * 8 + 2 * c] = packh2(o[nf][2] * inv1, o[nf][3] * inv1);
    }
}

// ---------------------------------------------------------------------------
// Launch
// ---------------------------------------------------------------------------
extern "C" void kernel_launch(void* const* d_in, const int* in_sizes, int n_in,
                              void* d_out, int out_size)
{
    const float* queries = (const float*)d_in[0];
    const unsigned char* mask = (const unsigned char*)d_in[1];
    const float* Wq = (const float*)d_in[2];
    const float* Wk = (const float*)d_in[3];
    const float* Wc = (const float*)d_in[4];
    float* out = (float*)d_out;

    __half *xh, *wqh, *wkh, *wch, *qh, *kh, *oh;
    cudaGetSymbolAddress((void**)&xh, g_Xh);
    cudaGetSymbolAddress((void**)&wqh, g_Wqh);
    cudaGetSymbolAddress((void**)&wkh, g_Wkh);
    cudaGetSymbolAddress((void**)&wch, g_Wch);
    cudaGetSymbolAddress((void**)&qh, g_Qh);
    cudaGetSymbolAddress((void**)&kh, g_Kh);
    cudaGetSymbolAddress((void**)&oh, g_Oh);

    // 0) conversions + mask prep
    detect_mask_kind<<<1, 256>>>((const unsigned int*)mask);
    mask_to_bits<<<(BB * NN * (NN / 32)) / 256, 256>>>(mask);
    conv_all_kernel<<<(int)((XELEMS + 3 * WELEMS) / 8 / 256), 256>>>(
        queries, Wq, Wk, Wc);

    // 1) Qh = Xh @ (QSCALE*Wq)^T, Kh = Xh @ Wk^T (fused via z)
    dim3 gproj(BB * NN / 128, DD / 128, 2);
    gemm_h_kernel<<<gproj, 256>>>(xh, wqh, wkh, qh, kh, 1);

    // 2) attention (64 q / 128-thread blocks, 5 blocks/SM target)
    dim3 gattn(NN / 64, HH, BB);
    attn_h_kernel<<<gattn, 128>>>();

    // 3) out = Oh @ Wc^T (fp32 out)
    dim3 gepi(BB * NN / 128, DD / 128, 1);
    gemm_h_kernel<<<gepi, 256>>>(oh, wch, wch, out, out, 0);
}